// round 1
// baseline (speedup 1.0000x reference)
#include <cuda_runtime.h>
#include <math.h>

#define Bb    8
#define NPIX  256
#define Mm    8192
#define N_CP  24576
#define N_CA  24576

// Precomputed DFT phase tables (sanctioned __device__ scratch, ~33.5 MB total)
__device__ float g_Evre[Mm * NPIX];
__device__ float g_Evim[Mm * NPIX];
__device__ float g_Eure[Mm * NPIX];
__device__ float g_Euim[Mm * NPIX];

// Accurate sincos regardless of --use_fast_math: reduce fp32 angle into
// [-pi, pi] in double, then sincosf (fast-math variant is accurate in-range).
__device__ __forceinline__ void safe_sincos(float ang, float* s, float* c) {
    double r = remainder((double)ang, 6.283185307179586476925286766559);
    float rf = (float)r;
    sincosf(rf, s, c);
}

__global__ void phase_kernel(const float* __restrict__ ktraj) {
    int idx = blockIdx.x * blockDim.x + threadIdx.x;
    if (idx >= Mm * NPIX) return;
    int m = idx >> 8;
    int j = idx & 255;
    float coord = (float)(j - NPIX / 2);
    float kv = ktraj[m];
    float ku = ktraj[Mm + m];
    float sv, cv, su, cu;
    safe_sincos(-kv * coord, &sv, &cv);
    safe_sincos(-ku * coord, &su, &cu);
    g_Evre[idx] = cv;  g_Evim[idx] = sv;
    g_Eure[idx] = cu;  g_Euim[idx] = su;
}

// Fused bilinear kernel: block = 32 m-values x 1 batch, 256 threads (8 warps).
// warp w owns m_local = 4w..4w+3 ; lane owns x in {4*lane..4*lane+3} U {128+4*lane..+3}
__global__ __launch_bounds__(256) void vis_kernel(
    const float* __restrict__ images,
    const float* __restrict__ pulsefac,
    float* __restrict__ out)
{
    __shared__ __align__(16) float img_s[32][NPIX];   // 32 KB
    __shared__ __align__(8)  float2 ev_s[32][32];     // 8 KB  [m_local][y]

    const int tid  = threadIdx.x;
    const int w    = tid >> 5;
    const int lane = tid & 31;
    const int b    = blockIdx.y;
    const int m0   = blockIdx.x * 32;
    const int xa   = lane * 4;
    const int xb   = 128 + lane * 4;

    float tre[4][8], tim[4][8];
    #pragma unroll
    for (int mi = 0; mi < 4; mi++)
        #pragma unroll
        for (int j = 0; j < 8; j++) { tre[mi][j] = 0.f; tim[mi][j] = 0.f; }

    for (int yc = 0; yc < NPIX; yc += 32) {
        // stage img[b, yc:yc+32, :] into smem (coalesced float4)
        const float4* src = reinterpret_cast<const float4*>(
            images + ((size_t)b * NPIX + yc) * NPIX);
        float4* dst = reinterpret_cast<float4*>(&img_s[0][0]);
        #pragma unroll
        for (int i = tid; i < 32 * NPIX / 4; i += 256) dst[i] = src[i];
        // stage Ev[m0:m0+32, yc:yc+32]
        for (int i = tid; i < 32 * 32; i += 256) {
            int ml = i >> 5, y = i & 31;
            int gi = (m0 + ml) * NPIX + yc + y;
            ev_s[ml][y] = make_float2(g_Evre[gi], g_Evim[gi]);
        }
        __syncthreads();

        #pragma unroll 4
        for (int y = 0; y < 32; y++) {
            float4 ia = *reinterpret_cast<const float4*>(&img_s[y][xa]);
            float4 ib = *reinterpret_cast<const float4*>(&img_s[y][xb]);
            float im[8] = { ia.x, ia.y, ia.z, ia.w, ib.x, ib.y, ib.z, ib.w };
            #pragma unroll
            for (int mi = 0; mi < 4; mi++) {
                float2 e = ev_s[w * 4 + mi][y];
                #pragma unroll
                for (int j = 0; j < 8; j++) {
                    tre[mi][j] = fmaf(e.x, im[j], tre[mi][j]);
                    tim[mi][j] = fmaf(e.y, im[j], tim[mi][j]);
                }
            }
        }
        __syncthreads();
    }

    // Epilogue: kdata[b,m] = sum_x t[x] * Eu[m,x]  (complex*complex)
    #pragma unroll
    for (int mi = 0; mi < 4; mi++) {
        int m = m0 + w * 4 + mi;
        const float* eur = &g_Eure[m * NPIX];
        const float* eui = &g_Euim[m * NPIX];
        float pr = 0.f, pi = 0.f;
        #pragma unroll
        for (int j = 0; j < 4; j++) {
            float er = eur[xa + j], ei = eui[xa + j];
            pr = fmaf(tre[mi][j], er, pr);  pr = fmaf(-tim[mi][j], ei, pr);
            pi = fmaf(tre[mi][j], ei, pi);  pi = fmaf( tim[mi][j], er, pi);
            er = eur[xb + j];  ei = eui[xb + j];
            pr = fmaf(tre[mi][4 + j], er, pr);  pr = fmaf(-tim[mi][4 + j], ei, pr);
            pi = fmaf(tre[mi][4 + j], ei, pi);  pi = fmaf( tim[mi][4 + j], er, pi);
        }
        #pragma unroll
        for (int s = 16; s > 0; s >>= 1) {
            pr += __shfl_xor_sync(0xffffffffu, pr, s);
            pi += __shfl_xor_sync(0xffffffffu, pi, s);
        }
        if (lane == 0) {
            float pfr = pulsefac[m], pfi = pulsefac[Mm + m];
            float vr = pr * pfr - pi * pfi;
            float vi = pr * pfi + pi * pfr;
            out[(size_t)b * 2 * Mm + m]      = vr;              // vis[b,0,m]
            out[(size_t)b * 2 * Mm + Mm + m] = vi;              // vis[b,1,m]
            out[(size_t)Bb * 2 * Mm + (size_t)b * Mm + m] =     // visamp[b,m]
                sqrtf(vr * vr + vi * vi + 1e-16f);
        }
    }
}

__global__ void cphase_kernel(const float* __restrict__ sign,
                              const int* __restrict__ ind,
                              const float* __restrict__ vis,
                              float* __restrict__ out_cp)
{
    int idx = blockIdx.x * blockDim.x + threadIdx.x;
    if (idx >= Bb * N_CP) return;
    int b = idx / N_CP;
    int n = idx - b * N_CP;
    float s = 0.f;
    #pragma unroll
    for (int k = 0; k < 3; k++) {
        int m = ind[k * N_CP + n];
        float vr = vis[(size_t)b * 2 * Mm + m];
        float vi = vis[(size_t)b * 2 * Mm + Mm + m];
        s = fmaf(sign[k * N_CP + n], atan2f(vi, vr), s);
    }
    out_cp[idx] = s * 57.29577951308232f;  // float32(180/pi)
}

__global__ void camp_kernel(const int* __restrict__ ind,
                            const float* __restrict__ vis,
                            float* __restrict__ out_lc)
{
    int idx = blockIdx.x * blockDim.x + threadIdx.x;
    if (idx >= Bb * N_CA) return;
    int b = idx / N_CA;
    int n = idx - b * N_CA;
    float a[4];
    #pragma unroll
    for (int k = 0; k < 4; k++) {
        int m = ind[k * N_CA + n];
        float vr = vis[(size_t)b * 2 * Mm + m];
        float vi = vis[(size_t)b * 2 * Mm + Mm + m];
        a[k] = sqrtf(vr * vr + vi * vi + 1e-16f);
    }
    out_lc[idx] = logf(a[0]) + logf(a[1]) - logf(a[2]) - logf(a[3]);
}

extern "C" void kernel_launch(void* const* d_in, const int* in_sizes, int n_in,
                              void* d_out, int out_size)
{
    const float* images      = (const float*)d_in[0];
    const float* ktraj       = (const float*)d_in[1];
    const float* pulsefac    = (const float*)d_in[2];
    const float* cphase_sign = (const float*)d_in[3];
    const int*   cphase_ind  = (const int*)d_in[4];
    const int*   camp_ind    = (const int*)d_in[5];
    float* out = (float*)d_out;

    float* out_vis    = out;                                   // B*2*M
    float* out_cp     = out + (size_t)Bb * 2 * Mm + (size_t)Bb * Mm;
    float* out_lc     = out_cp + (size_t)Bb * N_CP;

    phase_kernel<<<(Mm * NPIX + 255) / 256, 256>>>(ktraj);

    dim3 grid(Mm / 32, Bb);
    vis_kernel<<<grid, 256>>>(images, pulsefac, out);

    cphase_kernel<<<(Bb * N_CP + 255) / 256, 256>>>(cphase_sign, cphase_ind, out_vis, out_cp);
    camp_kernel<<<(Bb * N_CA + 255) / 256, 256>>>(camp_ind, out_vis, out_lc);
}

// round 6
// speedup vs baseline: 2.0230x; 2.0230x over previous
#include <cuda_runtime.h>
#include <cuda_bf16.h>
#include <cstdint>
#include <math.h>

#define Bb    8
#define NPIX  256
#define Mm    8192
#define N_CP  24576
#define N_CA  24576
#define ROWS2 16384          // 2*Mm (re rows then im rows)
#define TILES 128            // ROWS2 / 128

// ---------------- device scratch (static, allowed) ----------------
// A packed: [tile][chunk][hi,lo][128 rows x 64 k bf16, SW128 swizzled] = 16 MB
__device__ __align__(1024) unsigned char g_Apack[(size_t)TILES * 4 * 2 * 16384];
// B packed: [b][chunk][hi,lo][256 rows(x) x 64 k(y) bf16, swizzled]    = 2 MB
__device__ __align__(1024) unsigned char g_Bpack[(size_t)Bb * 4 * 2 * 32768];
__device__ float g_Eur[Mm * NPIX];
__device__ float g_Eui[Mm * NPIX];
// partial sums: [row(16384)][b(8)][n-warp(4)]
__device__ float g_p1[(size_t)ROWS2 * Bb * 4];
__device__ float g_p2[(size_t)ROWS2 * Bb * 4];

// ---------------- helpers ----------------
__device__ __forceinline__ uint32_t smem_u32(const void* p) {
    uint32_t a;
    asm("{ .reg .u64 t; cvta.to.shared.u64 t, %1; cvt.u32.u64 %0, t; }" : "=r"(a) : "l"(p));
    return a;
}
__device__ __forceinline__ void cpasync16(uint32_t dst, const void* src) {
    asm volatile("cp.async.cg.shared.global [%0], [%1], 16;" :: "r"(dst), "l"(src));
}
__device__ __forceinline__ unsigned swz(unsigned off) { return off ^ ((off >> 3) & 0x70); }

#define LDSM_X4(r0, r1, r2, r3, a) \
    asm volatile("ldmatrix.sync.aligned.m8n8.x4.shared.b16 {%0,%1,%2,%3}, [%4];" \
                 : "=r"(r0), "=r"(r1), "=r"(r2), "=r"(r3) : "r"(a))

#define MMA_BF16(d, a0, a1, a2, a3, b0, b1) \
    asm volatile("mma.sync.aligned.m16n8k16.row.col.f32.bf16.bf16.f32 " \
                 "{%0,%1,%2,%3},{%4,%5,%6,%7},{%8,%9},{%0,%1,%2,%3};" \
                 : "+f"((d)[0]), "+f"((d)[1]), "+f"((d)[2]), "+f"((d)[3]) \
                 : "r"(a0), "r"(a1), "r"(a2), "r"(a3), "r"(b0), "r"(b1))

// ---------------- phase tables + A packing ----------------
__global__ void phase_kernel(const float* __restrict__ kt) {
    int idx = blockIdx.x * blockDim.x + threadIdx.x;
    if (idx >= Mm * NPIX) return;
    int m = idx >> 8, j = idx & 255;
    float coord = (float)(j - 128);
    float kv = kt[m], ku = kt[Mm + m];
    const double TP = 6.283185307179586476925286766559;
    float av = -kv * coord, au = -ku * coord;
    float nv = rintf(av * 0.15915494309189535f);
    float nu = rintf(au * 0.15915494309189535f);
    float rv = (float)((double)av - (double)nv * TP);
    float ru = (float)((double)au - (double)nu * TP);
    float sv, cv, su, cu;
    sincosf(rv, &sv, &cv);
    sincosf(ru, &su, &cu);
    g_Eur[idx] = cu;  g_Eui[idx] = su;
    int chunk = j >> 6, kk = j & 63;
    // A rows: row m = Ev real, row m+Mm = Ev imag
    #pragma unroll
    for (int p = 0; p < 2; p++) {
        int r2 = m + p * Mm;
        float v = p ? sv : cv;
        int tile = r2 >> 7, r = r2 & 127;
        unsigned off = swz((unsigned)(r * 128 + kk * 2));
        size_t base = ((size_t)(tile * 4 + chunk) * 2) * 16384;
        __nv_bfloat16 hi = __float2bfloat16(v);
        __nv_bfloat16 lo = __float2bfloat16(v - __bfloat162float(hi));
        *(__nv_bfloat16*)(g_Apack + base + off)         = hi;
        *(__nv_bfloat16*)(g_Apack + base + 16384 + off) = lo;
    }
}

// ---------------- B packing: B[n=x][k=y] = img[b,y,x] ----------------
__global__ void bpack_kernel(const float* __restrict__ img) {
    int idx = blockIdx.x * blockDim.x + threadIdx.x;
    if (idx >= Bb * NPIX * NPIX) return;
    int b = idx >> 16, rem = idx & 65535;
    int y = rem >> 8, x = rem & 255;
    float v = img[idx];
    int chunk = y >> 6, kk = y & 63;
    unsigned off = swz((unsigned)(x * 128 + kk * 2));
    size_t base = ((size_t)(b * 4 + chunk) * 2) * 32768;
    __nv_bfloat16 hi = __float2bfloat16(v);
    __nv_bfloat16 lo = __float2bfloat16(v - __bfloat162float(hi));
    *(__nv_bfloat16*)(g_Bpack + base + off)         = hi;
    *(__nv_bfloat16*)(g_Bpack + base + 32768 + off) = lo;
}

// ---------------- main GEMM (mma.sync HMMA) + fused Eu epilogue ----------------
// smem stage: [Ah 16K][Al 16K][Bh 32K][Bl 32K] = 96 KB, double buffered = 192 KB
#define SMEM_STAGE 98304
#define SMEM_TOT   196608

__device__ __forceinline__ void load_chunk(uint32_t sb, int stage, int tile, int cc, int tid) {
    int b = cc >> 2, c = cc & 3;
    uint32_t dst = sb + stage * SMEM_STAGE;
    const float4* srcA = (const float4*)(g_Apack + (size_t)(tile * 4 + c) * 32768);
    #pragma unroll
    for (int i = 0; i < 4; i++) cpasync16(dst + (tid + i * 512) * 16, srcA + tid + i * 512);
    uint32_t dstB = dst + 32768;
    const float4* srcB = (const float4*)(g_Bpack + (size_t)(b * 4 + c) * 65536);
    #pragma unroll
    for (int i = 0; i < 8; i++) cpasync16(dstB + (tid + i * 512) * 16, srcB + tid + i * 512);
    asm volatile("cp.async.commit_group;" ::: "memory");
}

__global__ __launch_bounds__(512, 1) void vis_mma_kernel() {
    extern __shared__ unsigned char smem[];
    uint32_t sb = smem_u32(smem);
    const int tid  = threadIdx.x;
    const int warp = tid >> 5, lane = tid & 31;
    const int wm   = warp & 3;         // M warp (32 rows each)
    const int wn   = warp >> 2;        // N warp (64 cols each)
    const int tile = blockIdx.x;

    // per-lane ldmatrix address components
    const uint32_t kA2 = (lane >> 4) * 16;           // A k byte-offset part
    const uint32_t kB2 = ((lane >> 3) & 1) * 16;     // B k byte-offset part
    uint32_t aRow[2], aXor[2], bRow[4], bXor[4];
    #pragma unroll
    for (int mt = 0; mt < 2; mt++) {
        int r = wm * 32 + mt * 16 + (lane & 15);
        aRow[mt] = r * 128;  aXor[mt] = (r & 7) << 4;
    }
    #pragma unroll
    for (int p = 0; p < 4; p++) {
        int r = wn * 64 + p * 16 + ((lane >> 4) & 1) * 8 + (lane & 7);
        bRow[p] = r * 128;  bXor[p] = (r & 7) << 4;
    }

    float acc[64];
    #pragma unroll
    for (int i = 0; i < 64; i++) acc[i] = 0.f;

    load_chunk(sb, 0, tile, 0, tid);
    load_chunk(sb, 1, tile, 1, tid);

    for (int cc = 0; cc < 32; cc++) {
        const int s = cc & 1, b = cc >> 2, c = cc & 3;
        if (cc + 2 < 32) asm volatile("cp.async.wait_group 1;" ::: "memory");
        else             asm volatile("cp.async.wait_group 0;" ::: "memory");
        __syncthreads();

        const uint32_t st = sb + s * SMEM_STAGE;
        #pragma unroll
        for (int ks = 0; ks < 4; ks++) {
            uint32_t ah[2][4], al[2][4];
            #pragma unroll
            for (int mt = 0; mt < 2; mt++) {
                uint32_t k2 = ks * 32 + kA2;
                uint32_t offH = st +         aRow[mt] + (k2 ^ aXor[mt]);
                uint32_t offL = st + 16384 + aRow[mt] + (k2 ^ aXor[mt]);
                LDSM_X4(ah[mt][0], ah[mt][1], ah[mt][2], ah[mt][3], offH);
                LDSM_X4(al[mt][0], al[mt][1], al[mt][2], al[mt][3], offL);
            }
            #pragma unroll
            for (int p = 0; p < 4; p++) {
                uint32_t k2 = ks * 32 + kB2;
                uint32_t offBH = st + 32768 + bRow[p] + (k2 ^ bXor[p]);
                uint32_t offBL = st + 65536 + bRow[p] + (k2 ^ bXor[p]);
                uint32_t h0, h1, h2, h3, l0, l1, l2, l3;
                LDSM_X4(h0, h1, h2, h3, offBH);
                #pragma unroll
                for (int mt = 0; mt < 2; mt++) {
                    MMA_BF16(&acc[(mt * 8 + 2 * p) * 4],     ah[mt][0], ah[mt][1], ah[mt][2], ah[mt][3], h0, h1);
                    MMA_BF16(&acc[(mt * 8 + 2 * p + 1) * 4], ah[mt][0], ah[mt][1], ah[mt][2], ah[mt][3], h2, h3);
                    MMA_BF16(&acc[(mt * 8 + 2 * p) * 4],     al[mt][0], al[mt][1], al[mt][2], al[mt][3], h0, h1);
                    MMA_BF16(&acc[(mt * 8 + 2 * p + 1) * 4], al[mt][0], al[mt][1], al[mt][2], al[mt][3], h2, h3);
                }
                LDSM_X4(l0, l1, l2, l3, offBL);
                #pragma unroll
                for (int mt = 0; mt < 2; mt++) {
                    MMA_BF16(&acc[(mt * 8 + 2 * p) * 4],     ah[mt][0], ah[mt][1], ah[mt][2], ah[mt][3], l0, l1);
                    MMA_BF16(&acc[(mt * 8 + 2 * p + 1) * 4], ah[mt][0], ah[mt][1], ah[mt][2], ah[mt][3], l2, l3);
                }
            }
        }

        if (c == 3) {
            // fused epilogue: p[row] = sum_x acc[row][x] * Eu[m, x]
            const int g = lane >> 2, t4 = lane & 3;
            #pragma unroll
            for (int mt = 0; mt < 2; mt++) {
                int r0 = tile * 128 + wm * 32 + mt * 16 + g;
                int mA = r0 & (Mm - 1);
                int mB = (r0 + 8) & (Mm - 1);
                const float* eurA = g_Eur + (size_t)mA * NPIX;
                const float* euiA = g_Eui + (size_t)mA * NPIX;
                const float* eurB = g_Eur + (size_t)mB * NPIX;
                const float* euiB = g_Eui + (size_t)mB * NPIX;
                float p1a = 0.f, p2a = 0.f, p1b = 0.f, p2b = 0.f;
                #pragma unroll
                for (int nt = 0; nt < 8; nt++) {
                    int x0 = wn * 64 + nt * 8 + t4 * 2;
                    float2 erA = *(const float2*)(eurA + x0);
                    float2 eiA = *(const float2*)(euiA + x0);
                    float2 erB = *(const float2*)(eurB + x0);
                    float2 eiB = *(const float2*)(euiB + x0);
                    float* d = &acc[(mt * 8 + nt) * 4];
                    p1a = fmaf(d[0], erA.x, fmaf(d[1], erA.y, p1a));
                    p2a = fmaf(d[0], eiA.x, fmaf(d[1], eiA.y, p2a));
                    p1b = fmaf(d[2], erB.x, fmaf(d[3], erB.y, p1b));
                    p2b = fmaf(d[2], eiB.x, fmaf(d[3], eiB.y, p2b));
                    d[0] = d[1] = d[2] = d[3] = 0.f;
                }
                #pragma unroll
                for (int sh = 1; sh <= 2; sh <<= 1) {
                    p1a += __shfl_xor_sync(0xffffffffu, p1a, sh);
                    p2a += __shfl_xor_sync(0xffffffffu, p2a, sh);
                    p1b += __shfl_xor_sync(0xffffffffu, p1b, sh);
                    p2b += __shfl_xor_sync(0xffffffffu, p2b, sh);
                }
                if (t4 == 0) {
                    size_t i1 = ((size_t)r0 * Bb + b) * 4 + wn;
                    size_t i2 = ((size_t)(r0 + 8) * Bb + b) * 4 + wn;
                    g_p1[i1] = p1a;  g_p2[i1] = p2a;
                    g_p1[i2] = p1b;  g_p2[i2] = p2b;
                }
            }
        }
        __syncthreads();
        if (cc + 2 < 32) load_chunk(sb, s, tile, cc + 2, tid);
    }
}

// ---------------- combine: partials -> kdata -> vis, visamp ----------------
__global__ void combine_kernel(const float* __restrict__ pf, float* __restrict__ out) {
    int idx = blockIdx.x * blockDim.x + threadIdx.x;
    if (idx >= Bb * Mm) return;
    int b = idx >> 13, m = idx & (Mm - 1);
    size_t i1 = ((size_t)m * Bb + b) * 4;
    size_t i2 = ((size_t)(m + Mm) * Bb + b) * 4;
    float trr = 0.f, tri = 0.f, tir = 0.f, tii = 0.f;
    #pragma unroll
    for (int w = 0; w < 4; w++) {
        trr += g_p1[i1 + w];  tri += g_p2[i1 + w];
        tir += g_p1[i2 + w];  tii += g_p2[i2 + w];
    }
    float kr = trr - tii, ki = tri + tir;
    float pr = pf[m], pi = pf[Mm + m];
    float vr = kr * pr - ki * pi;
    float vi = kr * pi + ki * pr;
    out[(size_t)b * 2 * Mm + m]      = vr;
    out[(size_t)b * 2 * Mm + Mm + m] = vi;
    out[(size_t)Bb * 2 * Mm + (size_t)b * Mm + m] = sqrtf(vr * vr + vi * vi + 1e-16f);
}

__global__ void cphase_kernel(const float* __restrict__ sign, const int* __restrict__ ind,
                              const float* __restrict__ vis, float* __restrict__ out_cp) {
    int idx = blockIdx.x * blockDim.x + threadIdx.x;
    if (idx >= Bb * N_CP) return;
    int b = idx / N_CP, n = idx - b * N_CP;
    float s = 0.f;
    #pragma unroll
    for (int k = 0; k < 3; k++) {
        int m = ind[k * N_CP + n];
        float vr = vis[(size_t)b * 2 * Mm + m];
        float vi = vis[(size_t)b * 2 * Mm + Mm + m];
        s = fmaf(sign[k * N_CP + n], atan2f(vi, vr), s);
    }
    out_cp[idx] = s * 57.29577951308232f;
}

__global__ void camp_kernel(const int* __restrict__ ind, const float* __restrict__ vis,
                            float* __restrict__ out_lc) {
    int idx = blockIdx.x * blockDim.x + threadIdx.x;
    if (idx >= Bb * N_CA) return;
    int b = idx / N_CA, n = idx - b * N_CA;
    float a[4];
    #pragma unroll
    for (int k = 0; k < 4; k++) {
        int m = ind[k * N_CA + n];
        float vr = vis[(size_t)b * 2 * Mm + m];
        float vi = vis[(size_t)b * 2 * Mm + Mm + m];
        a[k] = sqrtf(vr * vr + vi * vi + 1e-16f);
    }
    out_lc[idx] = logf(a[0]) + logf(a[1]) - logf(a[2]) - logf(a[3]);
}

extern "C" void kernel_launch(void* const* d_in, const int* in_sizes, int n_in,
                              void* d_out, int out_size) {
    const float* images      = (const float*)d_in[0];
    const float* ktraj       = (const float*)d_in[1];
    const float* pulsefac    = (const float*)d_in[2];
    const float* cphase_sign = (const float*)d_in[3];
    const int*   cphase_ind  = (const int*)d_in[4];
    const int*   camp_ind    = (const int*)d_in[5];
    float* out = (float*)d_out;

    float* out_vis = out;
    float* out_cp  = out + (size_t)Bb * 2 * Mm + (size_t)Bb * Mm;
    float* out_lc  = out_cp + (size_t)Bb * N_CP;

    cudaFuncSetAttribute(vis_mma_kernel, cudaFuncAttributeMaxDynamicSharedMemorySize, SMEM_TOT);

    phase_kernel<<<(Mm * NPIX + 255) / 256, 256>>>(ktraj);
    bpack_kernel<<<(Bb * NPIX * NPIX + 255) / 256, 256>>>(images);
    vis_mma_kernel<<<TILES, 512, SMEM_TOT>>>();
    combine_kernel<<<(Bb * Mm + 255) / 256, 256>>>(pulsefac, out);
    cphase_kernel<<<(Bb * N_CP + 255) / 256, 256>>>(cphase_sign, cphase_ind, out_vis, out_cp);
    camp_kernel<<<(Bb * N_CA + 255) / 256, 256>>>(camp_ind, out_vis, out_lc);
}

// round 7
// speedup vs baseline: 2.9204x; 1.4436x over previous
#include <cuda_runtime.h>
#include <cuda_bf16.h>
#include <cstdint>
#include <math.h>

#define Bb    8
#define NPIX  256
#define Mm    8192
#define N_CP  24576
#define N_CA  24576
#define ROWS2 16384          // 2*Mm (cos rows then sin rows)
#define TILES 128            // ROWS2 / 128

// ---------------- device scratch (static, allowed) ----------------
// A packed: [tile][chunk(2)][hi 16KB | lo 16KB]  (128 rows x 64 k bf16, SW128) = 8 MB
__device__ __align__(1024) unsigned char g_Apack[(size_t)TILES * 2 * 32768];
// B packed: [b][type(S,A)][chunk(2)][hi 32KB | lo 32KB] (256 x-rows x 64 k)    = 2 MB
__device__ __align__(1024) unsigned char g_Bpack[(size_t)Bb * 2 * 2 * 65536];
__device__ float g_Eur[Mm * NPIX];
__device__ float g_Eui[Mm * NPIX];
// partial sums: [row(16384)][b(8)][n-warp(4)]
__device__ float g_p1[(size_t)ROWS2 * Bb * 4];
__device__ float g_p2[(size_t)ROWS2 * Bb * 4];

// ---------------- helpers ----------------
__device__ __forceinline__ uint32_t smem_u32(const void* p) {
    uint32_t a;
    asm("{ .reg .u64 t; cvta.to.shared.u64 t, %1; cvt.u32.u64 %0, t; }" : "=r"(a) : "l"(p));
    return a;
}
__device__ __forceinline__ void cpasync16(uint32_t dst, const void* src) {
    asm volatile("cp.async.cg.shared.global [%0], [%1], 16;" :: "r"(dst), "l"(src));
}
__device__ __forceinline__ unsigned swz(unsigned off) { return off ^ ((off >> 3) & 0x70); }

#define LDSM_X4(r0, r1, r2, r3, a) \
    asm volatile("ldmatrix.sync.aligned.m8n8.x4.shared.b16 {%0,%1,%2,%3}, [%4];" \
                 : "=r"(r0), "=r"(r1), "=r"(r2), "=r"(r3) : "r"(a))

#define MMA_BF16(d, a0, a1, a2, a3, b0, b1) \
    asm volatile("mma.sync.aligned.m16n8k16.row.col.f32.bf16.bf16.f32 " \
                 "{%0,%1,%2,%3},{%4,%5,%6,%7},{%8,%9},{%0,%1,%2,%3};" \
                 : "+f"((d)[0]), "+f"((d)[1]), "+f"((d)[2]), "+f"((d)[3]) \
                 : "r"(a0), "r"(a1), "r"(a2), "r"(a3), "r"(b0), "r"(b1))

__device__ __forceinline__ float reduce_pi(float a) {
    const double TP = 6.283185307179586476925286766559;
    float n = rintf(a * 0.15915494309189535f);
    return (float)((double)a - (double)n * TP);
}

// ---------------- phase tables + A packing ----------------
// A rows: row m (cos type):  Ac[m,t] =  cos(kv*t),  t=1..128 at k-index t-1
//         row m+Mm (sin):    As[m,t] = -sin(kv*t)
__global__ void phase_kernel(const float* __restrict__ kt) {
    int idx = blockIdx.x * blockDim.x + threadIdx.x;
    if (idx >= Mm * NPIX) return;
    int m = idx >> 8, j = idx & 255;
    float kv = kt[m], ku = kt[Mm + m];
    // Eu table (x-dim), coord = j-128
    {
        float coord = (float)(j - 128);
        float au = -ku * coord;
        float su, cu;
        sincosf(reduce_pi(au), &su, &cu);
        g_Eur[idx] = cu;  g_Eui[idx] = su;
    }
    if (j < 128) {
        int t = j + 1;                 // 1..128
        float av = kv * (float)t;
        float sv, cv;
        sincosf(reduce_pi(av), &sv, &cv);
        int chunk = j >> 6, kk = j & 63;
        unsigned offc;
        // cos row
        {
            int tile = m >> 7, r = m & 127;
            offc = swz((unsigned)(r * 128 + kk * 2));
            size_t base = (size_t)(tile * 2 + chunk) * 32768;
            __nv_bfloat16 hi = __float2bfloat16(cv);
            __nv_bfloat16 lo = __float2bfloat16(cv - __bfloat162float(hi));
            *(__nv_bfloat16*)(g_Apack + base + offc)         = hi;
            *(__nv_bfloat16*)(g_Apack + base + 16384 + offc) = lo;
        }
        // sin row (value -sin)
        {
            float v = -sv;
            int tile = 64 + (m >> 7), r = m & 127;
            size_t base = (size_t)(tile * 2 + chunk) * 32768;
            __nv_bfloat16 hi = __float2bfloat16(v);
            __nv_bfloat16 lo = __float2bfloat16(v - __bfloat162float(hi));
            *(__nv_bfloat16*)(g_Apack + base + offc)         = hi;
            *(__nv_bfloat16*)(g_Apack + base + 16384 + offc) = lo;
        }
    }
}

// ---------------- B packing: folded image ----------------
// BS[b,t,x] = img[b,128+t,x] + img[b,128-t,x]   (t=1..128, img[256]:=0)
// BA[b,t,x] = img[b,128+t,x] - img[b,128-t,x]
__global__ void bpack_kernel(const float* __restrict__ img) {
    int idx = blockIdx.x * blockDim.x + threadIdx.x;
    if (idx >= Bb * 128 * NPIX) return;
    int b = idx >> 15, rem = idx & 32767;
    int t1 = rem >> 8, x = rem & 255;       // t1 = t-1, 0..127
    int t = t1 + 1;
    const float* ib = img + (size_t)b * NPIX * NPIX;
    float top = (t < 128) ? ib[(128 + t) * NPIX + x] : 0.f;
    float bot = ib[(128 - t) * NPIX + x];
    float vS = top + bot, vA = top - bot;
    int chunk = t1 >> 6, kk = t1 & 63;
    unsigned off = swz((unsigned)(x * 128 + kk * 2));
    #pragma unroll
    for (int type = 0; type < 2; type++) {
        float v = type ? vA : vS;
        size_t base = (size_t)((b * 2 + type) * 2 + chunk) * 65536;
        __nv_bfloat16 hi = __float2bfloat16(v);
        __nv_bfloat16 lo = __float2bfloat16(v - __bfloat162float(hi));
        *(__nv_bfloat16*)(g_Bpack + base + off)         = hi;
        *(__nv_bfloat16*)(g_Bpack + base + 32768 + off) = lo;
    }
}

// ---------------- main GEMM (mma.sync HMMA) + fused Eu epilogue ----------------
// smem stage: [Ah 16K][Al 16K][Bh 32K][Bl 32K] = 96 KB, double buffered = 192 KB
#define SMEM_STAGE 98304
#define SMEM_TOT   196608

__device__ __forceinline__ void load_chunk(uint32_t sb, int stage, int tile, int cc, int tid) {
    int b = cc >> 1, c = cc & 1;
    int type = (tile >= 64) ? 1 : 0;
    uint32_t dst = sb + stage * SMEM_STAGE;
    const float4* srcA = (const float4*)(g_Apack + (size_t)(tile * 2 + c) * 32768);
    #pragma unroll
    for (int i = 0; i < 4; i++) cpasync16(dst + (tid + i * 512) * 16, srcA + tid + i * 512);
    uint32_t dstB = dst + 32768;
    const float4* srcB = (const float4*)(g_Bpack + (size_t)((b * 2 + type) * 2 + c) * 65536);
    #pragma unroll
    for (int i = 0; i < 8; i++) cpasync16(dstB + (tid + i * 512) * 16, srcB + tid + i * 512);
    asm volatile("cp.async.commit_group;" ::: "memory");
}

__global__ __launch_bounds__(512, 1) void vis_mma_kernel(const float* __restrict__ images) {
    extern __shared__ unsigned char smem[];
    uint32_t sb = smem_u32(smem);
    const int tid  = threadIdx.x;
    const int warp = tid >> 5, lane = tid & 31;
    const int wm   = warp & 3;         // M warp (32 rows each)
    const int wn   = warp >> 2;        // N warp (64 cols each)
    const int tile = blockIdx.x;
    const bool isCos = tile < 64;

    const uint32_t kA2 = (lane >> 4) * 16;
    const uint32_t kB2 = ((lane >> 3) & 1) * 16;
    uint32_t aRow[2], aXor[2], bRow[4], bXor[4];
    #pragma unroll
    for (int mt = 0; mt < 2; mt++) {
        int r = wm * 32 + mt * 16 + (lane & 15);
        aRow[mt] = r * 128;  aXor[mt] = (r & 7) << 4;
    }
    #pragma unroll
    for (int p = 0; p < 4; p++) {
        int r = wn * 64 + p * 16 + ((lane >> 4) & 1) * 8 + (lane & 7);
        bRow[p] = r * 128;  bXor[p] = (r & 7) << 4;
    }

    float acc[64];
    #pragma unroll
    for (int i = 0; i < 64; i++) acc[i] = 0.f;

    load_chunk(sb, 0, tile, 0, tid);
    load_chunk(sb, 1, tile, 1, tid);

    for (int cc = 0; cc < 16; cc++) {
        const int s = cc & 1, b = cc >> 1, c = cc & 1;
        if (cc + 2 < 16) asm volatile("cp.async.wait_group 1;" ::: "memory");
        else             asm volatile("cp.async.wait_group 0;" ::: "memory");
        __syncthreads();

        const uint32_t st = sb + s * SMEM_STAGE;
        #pragma unroll
        for (int ks = 0; ks < 4; ks++) {
            uint32_t ah[2][4], al[2][4];
            #pragma unroll
            for (int mt = 0; mt < 2; mt++) {
                uint32_t k2 = ks * 32 + kA2;
                uint32_t offH = st +         aRow[mt] + (k2 ^ aXor[mt]);
                uint32_t offL = st + 16384 + aRow[mt] + (k2 ^ aXor[mt]);
                LDSM_X4(ah[mt][0], ah[mt][1], ah[mt][2], ah[mt][3], offH);
                LDSM_X4(al[mt][0], al[mt][1], al[mt][2], al[mt][3], offL);
            }
            #pragma unroll
            for (int p = 0; p < 4; p++) {
                uint32_t k2 = ks * 32 + kB2;
                uint32_t offBH = st + 32768 + bRow[p] + (k2 ^ bXor[p]);
                uint32_t offBL = st + 65536 + bRow[p] + (k2 ^ bXor[p]);
                uint32_t h0, h1, h2, h3, l0, l1, l2, l3;
                LDSM_X4(h0, h1, h2, h3, offBH);
                #pragma unroll
                for (int mt = 0; mt < 2; mt++) {
                    MMA_BF16(&acc[(mt * 8 + 2 * p) * 4],     ah[mt][0], ah[mt][1], ah[mt][2], ah[mt][3], h0, h1);
                    MMA_BF16(&acc[(mt * 8 + 2 * p + 1) * 4], ah[mt][0], ah[mt][1], ah[mt][2], ah[mt][3], h2, h3);
                    MMA_BF16(&acc[(mt * 8 + 2 * p) * 4],     al[mt][0], al[mt][1], al[mt][2], al[mt][3], h0, h1);
                    MMA_BF16(&acc[(mt * 8 + 2 * p + 1) * 4], al[mt][0], al[mt][1], al[mt][2], al[mt][3], h2, h3);
                }
                LDSM_X4(l0, l1, l2, l3, offBL);
                #pragma unroll
                for (int mt = 0; mt < 2; mt++) {
                    MMA_BF16(&acc[(mt * 8 + 2 * p) * 4],     ah[mt][0], ah[mt][1], ah[mt][2], ah[mt][3], l0, l1);
                    MMA_BF16(&acc[(mt * 8 + 2 * p + 1) * 4], ah[mt][0], ah[mt][1], ah[mt][2], ah[mt][3], l2, l3);
                }
            }
        }

        if (c == 1) {
            // epilogue: p[row] = sum_x (acc[row][x] (+ img[b,128,x] for cos rows)) * Eu[m, x]
            const int g = lane >> 2, t4 = lane & 3;
            float2 imgc[8];
            if (isCos) {
                const float* ir = images + ((size_t)b * NPIX + 128) * NPIX;
                #pragma unroll
                for (int nt = 0; nt < 8; nt++)
                    imgc[nt] = *(const float2*)(ir + wn * 64 + nt * 8 + t4 * 2);
            }
            #pragma unroll
            for (int mt = 0; mt < 2; mt++) {
                int r0 = tile * 128 + wm * 32 + mt * 16 + g;
                int mA = r0 & (Mm - 1);
                int mB = (r0 + 8) & (Mm - 1);
                const float* eurA = g_Eur + (size_t)mA * NPIX;
                const float* euiA = g_Eui + (size_t)mA * NPIX;
                const float* eurB = g_Eur + (size_t)mB * NPIX;
                const float* euiB = g_Eui + (size_t)mB * NPIX;
                float p1a = 0.f, p2a = 0.f, p1b = 0.f, p2b = 0.f;
                #pragma unroll
                for (int nt = 0; nt < 8; nt++) {
                    int x0 = wn * 64 + nt * 8 + t4 * 2;
                    float2 erA = *(const float2*)(eurA + x0);
                    float2 eiA = *(const float2*)(euiA + x0);
                    float2 erB = *(const float2*)(eurB + x0);
                    float2 eiB = *(const float2*)(euiB + x0);
                    float* d = &acc[(mt * 8 + nt) * 4];
                    if (isCos) {
                        d[0] += imgc[nt].x;  d[1] += imgc[nt].y;
                        d[2] += imgc[nt].x;  d[3] += imgc[nt].y;
                    }
                    p1a = fmaf(d[0], erA.x, fmaf(d[1], erA.y, p1a));
                    p2a = fmaf(d[0], eiA.x, fmaf(d[1], eiA.y, p2a));
                    p1b = fmaf(d[2], erB.x, fmaf(d[3], erB.y, p1b));
                    p2b = fmaf(d[2], eiB.x, fmaf(d[3], eiB.y, p2b));
                    d[0] = d[1] = d[2] = d[3] = 0.f;
                }
                #pragma unroll
                for (int sh = 1; sh <= 2; sh <<= 1) {
                    p1a += __shfl_xor_sync(0xffffffffu, p1a, sh);
                    p2a += __shfl_xor_sync(0xffffffffu, p2a, sh);
                    p1b += __shfl_xor_sync(0xffffffffu, p1b, sh);
                    p2b += __shfl_xor_sync(0xffffffffu, p2b, sh);
                }
                if (t4 == 0) {
                    size_t i1 = ((size_t)r0 * Bb + b) * 4 + wn;
                    size_t i2 = ((size_t)(r0 + 8) * Bb + b) * 4 + wn;
                    g_p1[i1] = p1a;  g_p2[i1] = p2a;
                    g_p1[i2] = p1b;  g_p2[i2] = p2b;
                }
            }
        }
        __syncthreads();
        if (cc + 2 < 16) load_chunk(sb, s, tile, cc + 2, tid);
    }
}

// ---------------- combine: partials -> kdata -> vis, visamp ----------------
__global__ void combine_kernel(const float* __restrict__ pf, float* __restrict__ out) {
    int idx = blockIdx.x * blockDim.x + threadIdx.x;
    if (idx >= Bb * Mm) return;
    int b = idx >> 13, m = idx & (Mm - 1);
    size_t i1 = ((size_t)m * Bb + b) * 4;
    size_t i2 = ((size_t)(m + Mm) * Bb + b) * 4;
    float4 q1 = *(const float4*)(g_p1 + i1);
    float4 q2 = *(const float4*)(g_p2 + i1);
    float4 q3 = *(const float4*)(g_p1 + i2);
    float4 q4 = *(const float4*)(g_p2 + i2);
    float trr = q1.x + q1.y + q1.z + q1.w;   // sum tmp_re * Eur
    float tri = q2.x + q2.y + q2.z + q2.w;   // sum tmp_re * Eui
    float tir = q3.x + q3.y + q3.z + q3.w;   // sum tmp_im * Eur
    float tii = q4.x + q4.y + q4.z + q4.w;   // sum tmp_im * Eui
    float kr = trr - tii, ki = tri + tir;
    float pr = pf[m], pi = pf[Mm + m];
    float vr = kr * pr - ki * pi;
    float vi = kr * pi + ki * pr;
    out[(size_t)b * 2 * Mm + m]      = vr;
    out[(size_t)b * 2 * Mm + Mm + m] = vi;
    out[(size_t)Bb * 2 * Mm + (size_t)b * Mm + m] = sqrtf(vr * vr + vi * vi + 1e-16f);
}

// ---------------- fused cphase + logcamp ----------------
__global__ void obs_kernel(const float* __restrict__ sign, const int* __restrict__ cind,
                           const int* __restrict__ aind, const float* __restrict__ vis,
                           float* __restrict__ out_cp, float* __restrict__ out_lc) {
    int idx = blockIdx.x * blockDim.x + threadIdx.x;
    if (idx < Bb * N_CP) {
        int b = idx / N_CP, n = idx - b * N_CP;
        float s = 0.f;
        #pragma unroll
        for (int k = 0; k < 3; k++) {
            int m = cind[k * N_CP + n];
            float vr = vis[(size_t)b * 2 * Mm + m];
            float vi = vis[(size_t)b * 2 * Mm + Mm + m];
            s = fmaf(sign[k * N_CP + n], atan2f(vi, vr), s);
        }
        out_cp[idx] = s * 57.29577951308232f;
    } else {
        int j = idx - Bb * N_CP;
        if (j >= Bb * N_CA) return;
        int b = j / N_CA, n = j - b * N_CA;
        float a[4];
        #pragma unroll
        for (int k = 0; k < 4; k++) {
            int m = aind[k * N_CA + n];
            float vr = vis[(size_t)b * 2 * Mm + m];
            float vi = vis[(size_t)b * 2 * Mm + Mm + m];
            a[k] = sqrtf(vr * vr + vi * vi + 1e-16f);
        }
        out_lc[j] = logf(a[0]) + logf(a[1]) - logf(a[2]) - logf(a[3]);
    }
}

extern "C" void kernel_launch(void* const* d_in, const int* in_sizes, int n_in,
                              void* d_out, int out_size) {
    const float* images      = (const float*)d_in[0];
    const float* ktraj       = (const float*)d_in[1];
    const float* pulsefac    = (const float*)d_in[2];
    const float* cphase_sign = (const float*)d_in[3];
    const int*   cphase_ind  = (const int*)d_in[4];
    const int*   camp_ind    = (const int*)d_in[5];
    float* out = (float*)d_out;

    float* out_vis = out;
    float* out_cp  = out + (size_t)Bb * 2 * Mm + (size_t)Bb * Mm;
    float* out_lc  = out_cp + (size_t)Bb * N_CP;

    cudaFuncSetAttribute(vis_mma_kernel, cudaFuncAttributeMaxDynamicSharedMemorySize, SMEM_TOT);

    phase_kernel<<<(Mm * NPIX + 255) / 256, 256>>>(ktraj);
    bpack_kernel<<<(Bb * 128 * NPIX + 255) / 256, 256>>>(images);
    vis_mma_kernel<<<TILES, 512, SMEM_TOT>>>(images);
    combine_kernel<<<(Bb * Mm + 255) / 256, 256>>>(pulsefac, out);
    obs_kernel<<<(Bb * (N_CP + N_CA) + 255) / 256, 256>>>(cphase_sign, cphase_ind, camp_ind,
                                                          out_vis, out_cp, out_lc);
}

// round 8
// speedup vs baseline: 3.0398x; 1.0409x over previous
#include <cuda_runtime.h>
#include <cuda_bf16.h>
#include <cstdint>
#include <math.h>

#define Bb    8
#define NPIX  256
#define Mm    8192
#define N_CP  24576
#define N_CA  24576
#define ROWS2 16384          // 2*Mm (cos rows then sin rows)
#define TILES 128            // ROWS2 / 128

// ---------------- device scratch (static, allowed) ----------------
__device__ __align__(1024) unsigned char g_Apack[(size_t)TILES * 2 * 32768];
__device__ __align__(1024) unsigned char g_Bpack[(size_t)Bb * 2 * 2 * 65536];
__device__ float g_Eur[Mm * NPIX];
__device__ float g_Eui[Mm * NPIX];
__device__ float g_p1[(size_t)ROWS2 * Bb * 4];
__device__ float g_p2[(size_t)ROWS2 * Bb * 4];
__device__ float2 g_visc[(size_t)Bb * Mm];     // packed (re,im) for gathers

// ---------------- helpers ----------------
__device__ __forceinline__ uint32_t smem_u32(const void* p) {
    uint32_t a;
    asm("{ .reg .u64 t; cvta.to.shared.u64 t, %1; cvt.u32.u64 %0, t; }" : "=r"(a) : "l"(p));
    return a;
}
__device__ __forceinline__ void cpasync16(uint32_t dst, const void* src) {
    asm volatile("cp.async.cg.shared.global [%0], [%1], 16;" :: "r"(dst), "l"(src));
}
__device__ __forceinline__ unsigned swz(unsigned off) { return off ^ ((off >> 3) & 0x70); }

#define LDSM_X4(r0, r1, r2, r3, a) \
    asm volatile("ldmatrix.sync.aligned.m8n8.x4.shared.b16 {%0,%1,%2,%3}, [%4];" \
                 : "=r"(r0), "=r"(r1), "=r"(r2), "=r"(r3) : "r"(a))

#define MMA_BF16(d, a0, a1, a2, a3, b0, b1) \
    asm volatile("mma.sync.aligned.m16n8k16.row.col.f32.bf16.bf16.f32 " \
                 "{%0,%1,%2,%3},{%4,%5,%6,%7},{%8,%9},{%0,%1,%2,%3};" \
                 : "+f"((d)[0]), "+f"((d)[1]), "+f"((d)[2]), "+f"((d)[3]) \
                 : "r"(a0), "r"(a1), "r"(a2), "r"(a3), "r"(b0), "r"(b1))

__device__ __forceinline__ float reduce_pi(float a) {
    const double TP = 6.283185307179586476925286766559;
    float n = rintf(a * 0.15915494309189535f);
    return (float)((double)a - (double)n * TP);
}

// deg-11 minimax atan2 (max err ~1e-6 rad); inputs never both zero in practice
__device__ __forceinline__ float fast_atan2(float y, float x) {
    float ax = fabsf(x), ay = fabsf(y);
    float mx = fmaxf(ax, ay), mn = fminf(ax, ay);
    float t = __fdividef(mn, mx);
    float t2 = t * t;
    float p = -0.01172120f;
    p = fmaf(p, t2,  0.05265332f);
    p = fmaf(p, t2, -0.11643287f);
    p = fmaf(p, t2,  0.19354346f);
    p = fmaf(p, t2, -0.33262347f);
    p = fmaf(p, t2,  0.99997726f);
    float r = p * t;
    if (ay > ax) r = 1.57079632679f - r;
    if (x < 0.f) r = 3.14159265359f - r;
    return (y < 0.f) ? -r : r;
}

// ---------------- fused prep: phase tables + A pack + B pack ----------------
__global__ void prep_kernel(const float* __restrict__ kt, const float* __restrict__ img) {
    int idx = blockIdx.x * blockDim.x + threadIdx.x;
    if (idx < Mm * NPIX) {
        int m = idx >> 8, j = idx & 255;
        float kv = kt[m], ku = kt[Mm + m];
        {
            float coord = (float)(j - 128);
            float ru = reduce_pi(-ku * coord);
            g_Eur[idx] = __cosf(ru);
            g_Eui[idx] = __sinf(ru);
        }
        if (j < 128) {
            int t = j + 1;                 // 1..128
            float rv = reduce_pi(kv * (float)t);
            float cv = __cosf(rv), sv = __sinf(rv);
            int chunk = j >> 6, kk = j & 63;
            int r = m & 127;
            unsigned offc = swz((unsigned)(r * 128 + kk * 2));
            {   // cos row
                int tile = m >> 7;
                size_t base = (size_t)(tile * 2 + chunk) * 32768;
                __nv_bfloat16 hi = __float2bfloat16(cv);
                __nv_bfloat16 lo = __float2bfloat16(cv - __bfloat162float(hi));
                *(__nv_bfloat16*)(g_Apack + base + offc)         = hi;
                *(__nv_bfloat16*)(g_Apack + base + 16384 + offc) = lo;
            }
            {   // sin row (value -sin)
                float v = -sv;
                int tile = 64 + (m >> 7);
                size_t base = (size_t)(tile * 2 + chunk) * 32768;
                __nv_bfloat16 hi = __float2bfloat16(v);
                __nv_bfloat16 lo = __float2bfloat16(v - __bfloat162float(hi));
                *(__nv_bfloat16*)(g_Apack + base + offc)         = hi;
                *(__nv_bfloat16*)(g_Apack + base + 16384 + offc) = lo;
            }
        }
    } else {
        int k = idx - Mm * NPIX;
        if (k >= Bb * 128 * NPIX) return;
        int b = k >> 15, rem = k & 32767;
        int t1 = rem >> 8, x = rem & 255;       // t1 = t-1
        int t = t1 + 1;
        const float* ib = img + (size_t)b * NPIX * NPIX;
        float top = (t < 128) ? ib[(128 + t) * NPIX + x] : 0.f;
        float bot = ib[(128 - t) * NPIX + x];
        float vS = top + bot, vA = top - bot;
        int chunk = t1 >> 6, kk = t1 & 63;
        unsigned off = swz((unsigned)(x * 128 + kk * 2));
        #pragma unroll
        for (int type = 0; type < 2; type++) {
            float v = type ? vA : vS;
            size_t base = (size_t)((b * 2 + type) * 2 + chunk) * 65536;
            __nv_bfloat16 hi = __float2bfloat16(v);
            __nv_bfloat16 lo = __float2bfloat16(v - __bfloat162float(hi));
            *(__nv_bfloat16*)(g_Bpack + base + off)         = hi;
            *(__nv_bfloat16*)(g_Bpack + base + 32768 + off) = lo;
        }
    }
}

// ---------------- main GEMM (mma.sync HMMA) + fused Eu epilogue ----------------
#define SMEM_STAGE 98304
#define SMEM_TOT   196608

__device__ __forceinline__ void load_chunk(uint32_t sb, int stage, int tile, int cc, int tid) {
    int b = cc >> 1, c = cc & 1;
    int type = (tile >= 64) ? 1 : 0;
    uint32_t dst = sb + stage * SMEM_STAGE;
    const float4* srcA = (const float4*)(g_Apack + (size_t)(tile * 2 + c) * 32768);
    #pragma unroll
    for (int i = 0; i < 4; i++) cpasync16(dst + (tid + i * 512) * 16, srcA + tid + i * 512);
    uint32_t dstB = dst + 32768;
    const float4* srcB = (const float4*)(g_Bpack + (size_t)((b * 2 + type) * 2 + c) * 65536);
    #pragma unroll
    for (int i = 0; i < 8; i++) cpasync16(dstB + (tid + i * 512) * 16, srcB + tid + i * 512);
    asm volatile("cp.async.commit_group;" ::: "memory");
}

__global__ __launch_bounds__(512, 1) void vis_mma_kernel(const float* __restrict__ images) {
    extern __shared__ unsigned char smem[];
    uint32_t sb = smem_u32(smem);
    const int tid  = threadIdx.x;
    const int warp = tid >> 5, lane = tid & 31;
    const int wm   = warp & 3;
    const int wn   = warp >> 2;
    const int tile = blockIdx.x;
    const bool isCos = tile < 64;

    const uint32_t kA2 = (lane >> 4) * 16;
    const uint32_t kB2 = ((lane >> 3) & 1) * 16;
    uint32_t aRow[2], aXor[2], bRow[4], bXor[4];
    #pragma unroll
    for (int mt = 0; mt < 2; mt++) {
        int r = wm * 32 + mt * 16 + (lane & 15);
        aRow[mt] = r * 128;  aXor[mt] = (r & 7) << 4;
    }
    #pragma unroll
    for (int p = 0; p < 4; p++) {
        int r = wn * 64 + p * 16 + ((lane >> 4) & 1) * 8 + (lane & 7);
        bRow[p] = r * 128;  bXor[p] = (r & 7) << 4;
    }

    float acc[64];
    #pragma unroll
    for (int i = 0; i < 64; i++) acc[i] = 0.f;

    load_chunk(sb, 0, tile, 0, tid);
    load_chunk(sb, 1, tile, 1, tid);

    for (int cc = 0; cc < 16; cc++) {
        const int s = cc & 1, b = cc >> 1, c = cc & 1;
        if (cc + 2 < 16) asm volatile("cp.async.wait_group 1;" ::: "memory");
        else             asm volatile("cp.async.wait_group 0;" ::: "memory");
        __syncthreads();

        const uint32_t st = sb + s * SMEM_STAGE;
        #pragma unroll
        for (int ks = 0; ks < 4; ks++) {
            uint32_t ah[2][4], al[2][4];
            #pragma unroll
            for (int mt = 0; mt < 2; mt++) {
                uint32_t k2 = ks * 32 + kA2;
                uint32_t offH = st +         aRow[mt] + (k2 ^ aXor[mt]);
                uint32_t offL = st + 16384 + aRow[mt] + (k2 ^ aXor[mt]);
                LDSM_X4(ah[mt][0], ah[mt][1], ah[mt][2], ah[mt][3], offH);
                LDSM_X4(al[mt][0], al[mt][1], al[mt][2], al[mt][3], offL);
            }
            #pragma unroll
            for (int p = 0; p < 4; p++) {
                uint32_t k2 = ks * 32 + kB2;
                uint32_t offBH = st + 32768 + bRow[p] + (k2 ^ bXor[p]);
                uint32_t offBL = st + 65536 + bRow[p] + (k2 ^ bXor[p]);
                uint32_t h0, h1, h2, h3, l0, l1, l2, l3;
                LDSM_X4(h0, h1, h2, h3, offBH);
                #pragma unroll
                for (int mt = 0; mt < 2; mt++) {
                    MMA_BF16(&acc[(mt * 8 + 2 * p) * 4],     ah[mt][0], ah[mt][1], ah[mt][2], ah[mt][3], h0, h1);
                    MMA_BF16(&acc[(mt * 8 + 2 * p + 1) * 4], ah[mt][0], ah[mt][1], ah[mt][2], ah[mt][3], h2, h3);
                    MMA_BF16(&acc[(mt * 8 + 2 * p) * 4],     al[mt][0], al[mt][1], al[mt][2], al[mt][3], h0, h1);
                    MMA_BF16(&acc[(mt * 8 + 2 * p + 1) * 4], al[mt][0], al[mt][1], al[mt][2], al[mt][3], h2, h3);
                }
                LDSM_X4(l0, l1, l2, l3, offBL);
                #pragma unroll
                for (int mt = 0; mt < 2; mt++) {
                    MMA_BF16(&acc[(mt * 8 + 2 * p) * 4],     ah[mt][0], ah[mt][1], ah[mt][2], ah[mt][3], l0, l1);
                    MMA_BF16(&acc[(mt * 8 + 2 * p + 1) * 4], ah[mt][0], ah[mt][1], ah[mt][2], ah[mt][3], l2, l3);
                }
            }
        }

        if (c == 1) {
            const int g = lane >> 2, t4 = lane & 3;
            float2 imgc[8];
            if (isCos) {
                const float* ir = images + ((size_t)b * NPIX + 128) * NPIX;
                #pragma unroll
                for (int nt = 0; nt < 8; nt++)
                    imgc[nt] = *(const float2*)(ir + wn * 64 + nt * 8 + t4 * 2);
            }
            #pragma unroll
            for (int mt = 0; mt < 2; mt++) {
                int r0 = tile * 128 + wm * 32 + mt * 16 + g;
                int mA = r0 & (Mm - 1);
                int mB = (r0 + 8) & (Mm - 1);
                const float* eurA = g_Eur + (size_t)mA * NPIX;
                const float* euiA = g_Eui + (size_t)mA * NPIX;
                const float* eurB = g_Eur + (size_t)mB * NPIX;
                const float* euiB = g_Eui + (size_t)mB * NPIX;
                float p1a = 0.f, p2a = 0.f, p1b = 0.f, p2b = 0.f;
                #pragma unroll
                for (int nt = 0; nt < 8; nt++) {
                    int x0 = wn * 64 + nt * 8 + t4 * 2;
                    float2 erA = *(const float2*)(eurA + x0);
                    float2 eiA = *(const float2*)(euiA + x0);
                    float2 erB = *(const float2*)(eurB + x0);
                    float2 eiB = *(const float2*)(euiB + x0);
                    float* d = &acc[(mt * 8 + nt) * 4];
                    if (isCos) {
                        d[0] += imgc[nt].x;  d[1] += imgc[nt].y;
                        d[2] += imgc[nt].x;  d[3] += imgc[nt].y;
                    }
                    p1a = fmaf(d[0], erA.x, fmaf(d[1], erA.y, p1a));
                    p2a = fmaf(d[0], eiA.x, fmaf(d[1], eiA.y, p2a));
                    p1b = fmaf(d[2], erB.x, fmaf(d[3], erB.y, p1b));
                    p2b = fmaf(d[2], eiB.x, fmaf(d[3], eiB.y, p2b));
                    d[0] = d[1] = d[2] = d[3] = 0.f;
                }
                #pragma unroll
                for (int sh = 1; sh <= 2; sh <<= 1) {
                    p1a += __shfl_xor_sync(0xffffffffu, p1a, sh);
                    p2a += __shfl_xor_sync(0xffffffffu, p2a, sh);
                    p1b += __shfl_xor_sync(0xffffffffu, p1b, sh);
                    p2b += __shfl_xor_sync(0xffffffffu, p2b, sh);
                }
                if (t4 == 0) {
                    size_t i1 = ((size_t)r0 * Bb + b) * 4 + wn;
                    size_t i2 = ((size_t)(r0 + 8) * Bb + b) * 4 + wn;
                    g_p1[i1] = p1a;  g_p2[i1] = p2a;
                    g_p1[i2] = p1b;  g_p2[i2] = p2b;
                }
            }
        }
        __syncthreads();
        if (cc + 2 < 16) load_chunk(sb, s, tile, cc + 2, tid);
    }
}

// ---------------- combine: partials -> kdata -> vis, visamp, visc ----------------
__global__ void combine_kernel(const float* __restrict__ pf, float* __restrict__ out) {
    int idx = blockIdx.x * blockDim.x + threadIdx.x;
    if (idx >= Bb * Mm) return;
    int b = idx >> 13, m = idx & (Mm - 1);
    size_t i1 = ((size_t)m * Bb + b) * 4;
    size_t i2 = ((size_t)(m + Mm) * Bb + b) * 4;
    float4 q1 = *(const float4*)(g_p1 + i1);
    float4 q2 = *(const float4*)(g_p2 + i1);
    float4 q3 = *(const float4*)(g_p1 + i2);
    float4 q4 = *(const float4*)(g_p2 + i2);
    float trr = q1.x + q1.y + q1.z + q1.w;
    float tri = q2.x + q2.y + q2.z + q2.w;
    float tir = q3.x + q3.y + q3.z + q3.w;
    float tii = q4.x + q4.y + q4.z + q4.w;
    float kr = trr - tii, ki = tri + tir;
    float pr = pf[m], pi = pf[Mm + m];
    float vr = kr * pr - ki * pi;
    float vi = kr * pi + ki * pr;
    out[(size_t)b * 2 * Mm + m]      = vr;
    out[(size_t)b * 2 * Mm + Mm + m] = vi;
    out[(size_t)Bb * 2 * Mm + (size_t)b * Mm + m] = sqrtf(vr * vr + vi * vi + 1e-16f);
    g_visc[(size_t)b * Mm + m] = make_float2(vr, vi);
}

// ---------------- fused cphase + logcamp (fast transcendentals) ----------------
__global__ void obs_kernel(const float* __restrict__ sign, const int* __restrict__ cind,
                           const int* __restrict__ aind,
                           float* __restrict__ out_cp, float* __restrict__ out_lc) {
    int idx = blockIdx.x * blockDim.x + threadIdx.x;
    if (idx < Bb * N_CP) {
        int b = idx / N_CP, n = idx - b * N_CP;
        const float2* vb = g_visc + (size_t)b * Mm;
        float s = 0.f;
        #pragma unroll
        for (int k = 0; k < 3; k++) {
            float2 v = vb[cind[k * N_CP + n]];
            s = fmaf(sign[k * N_CP + n], fast_atan2(v.y, v.x), s);
        }
        out_cp[idx] = s * 57.29577951308232f;
    } else {
        int j = idx - Bb * N_CP;
        if (j >= Bb * N_CA) return;
        int b = j / N_CA, n = j - b * N_CA;
        const float2* vb = g_visc + (size_t)b * Mm;
        float s[4];
        #pragma unroll
        for (int k = 0; k < 4; k++) {
            float2 v = vb[aind[k * N_CA + n]];
            s[k] = fmaf(v.x, v.x, fmaf(v.y, v.y, 1e-16f));
        }
        out_lc[j] = 0.5f * (__logf(s[0]) + __logf(s[1]) - __logf(s[2]) - __logf(s[3]));
    }
}

extern "C" void kernel_launch(void* const* d_in, const int* in_sizes, int n_in,
                              void* d_out, int out_size) {
    const float* images      = (const float*)d_in[0];
    const float* ktraj       = (const float*)d_in[1];
    const float* pulsefac    = (const float*)d_in[2];
    const float* cphase_sign = (const float*)d_in[3];
    const int*   cphase_ind  = (const int*)d_in[4];
    const int*   camp_ind    = (const int*)d_in[5];
    float* out = (float*)d_out;

    float* out_cp = out + (size_t)Bb * 2 * Mm + (size_t)Bb * Mm;
    float* out_lc = out_cp + (size_t)Bb * N_CP;

    cudaFuncSetAttribute(vis_mma_kernel, cudaFuncAttributeMaxDynamicSharedMemorySize, SMEM_TOT);

    int prep_n = Mm * NPIX + Bb * 128 * NPIX;
    prep_kernel<<<(prep_n + 255) / 256, 256>>>(ktraj, images);
    vis_mma_kernel<<<TILES, 512, SMEM_TOT>>>(images);
    combine_kernel<<<(Bb * Mm + 255) / 256, 256>>>(pulsefac, out);
    obs_kernel<<<(Bb * (N_CP + N_CA) + 255) / 256, 256>>>(cphase_sign, cphase_ind, camp_ind,
                                                          out_cp, out_lc);
}

// round 9
// speedup vs baseline: 3.4742x; 1.1429x over previous
#include <cuda_runtime.h>
#include <cuda_bf16.h>
#include <cstdint>
#include <math.h>

#define Bb    8
#define NPIX  256
#define Mm    8192
#define N_CP  24576
#define N_CA  24576
#define ROWS2 16384          // 2*Mm (cos rows then sin rows)
#define TILES 128            // ROWS2 / 128

// ---------------- device scratch (static, allowed) ----------------
__device__ __align__(1024) unsigned char g_Apack[(size_t)TILES * 2 * 32768];
__device__ __align__(1024) unsigned char g_Bpack[(size_t)Bb * 2 * 2 * 65536];
__device__ float2 g_EuF[(size_t)Mm * 128];     // folded Eu table (C,S) per pair
__device__ float2 g_IcF[(size_t)Bb * 128];     // folded img center row per pair
__device__ float g_p1[(size_t)ROWS2 * Bb * 4];
__device__ float g_p2[(size_t)ROWS2 * Bb * 4];
__device__ float2 g_visc[(size_t)Bb * Mm];     // packed (re,im) for gathers

// ---------------- helpers ----------------
__device__ __forceinline__ uint32_t smem_u32(const void* p) {
    uint32_t a;
    asm("{ .reg .u64 t; cvta.to.shared.u64 t, %1; cvt.u32.u64 %0, t; }" : "=r"(a) : "l"(p));
    return a;
}
__device__ __forceinline__ void cpasync16(uint32_t dst, const void* src) {
    asm volatile("cp.async.cg.shared.global [%0], [%1], 16;" :: "r"(dst), "l"(src));
}
__device__ __forceinline__ unsigned swz(unsigned off) { return off ^ ((off >> 3) & 0x70); }

#define LDSM_X4(r0, r1, r2, r3, a) \
    asm volatile("ldmatrix.sync.aligned.m8n8.x4.shared.b16 {%0,%1,%2,%3}, [%4];" \
                 : "=r"(r0), "=r"(r1), "=r"(r2), "=r"(r3) : "r"(a))

#define MMA_BF16(d, a0, a1, a2, a3, b0, b1) \
    asm volatile("mma.sync.aligned.m16n8k16.row.col.f32.bf16.bf16.f32 " \
                 "{%0,%1,%2,%3},{%4,%5,%6,%7},{%8,%9},{%0,%1,%2,%3};" \
                 : "+f"((d)[0]), "+f"((d)[1]), "+f"((d)[2]), "+f"((d)[3]) \
                 : "r"(a0), "r"(a1), "r"(a2), "r"(a3), "r"(b0), "r"(b1))

__device__ __forceinline__ float reduce_pi(float a) {
    const double TP = 6.283185307179586476925286766559;
    float n = rintf(a * 0.15915494309189535f);
    return (float)((double)a - (double)n * TP);
}
__device__ __forceinline__ float fast_atan2(float y, float x) {
    float ax = fabsf(x), ay = fabsf(y);
    float mx = fmaxf(ax, ay), mn = fminf(ax, ay);
    float t = __fdividef(mn, mx);
    float t2 = t * t;
    float p = -0.01172120f;
    p = fmaf(p, t2,  0.05265332f);
    p = fmaf(p, t2, -0.11643287f);
    p = fmaf(p, t2,  0.19354346f);
    p = fmaf(p, t2, -0.33262347f);
    p = fmaf(p, t2,  0.99997726f);
    float r = p * t;
    if (ay > ax) r = 1.57079632679f - r;
    if (x < 0.f) r = 3.14159265359f - r;
    return (y < 0.f) ? -r : r;
}

// pair P -> x columns: lo = P+1 (P<127) else 0 ; hi = 255-P (P<127) else 128
__device__ __forceinline__ int lo_x(int P) { return (P < 127) ? (P + 1) : 0; }
__device__ __forceinline__ int hi_x(int P) { return (P < 127) ? (255 - P) : 128; }

// ---------------- fused prep: EuF + A pack + B pack + IcF ----------------
__global__ void prep_kernel(const float* __restrict__ kt, const float* __restrict__ img) {
    int idx = blockIdx.x * blockDim.x + threadIdx.x;
    if (idx < Mm * 128) {
        int m = idx >> 7, P = idx & 127;
        float kv = kt[m], ku = kt[Mm + m];
        // folded Eu: C = cos(ku*dd), S = sin(ku*dd), dd = 128 - lo_x(P)
        int dd = (P == 127) ? 128 : (127 - P);
        float ra = reduce_pi(ku * (float)dd);
        g_EuF[idx] = make_float2(__cosf(ra), __sinf(ra));
        // A rows at t = P+1
        int t = P + 1;
        float rv = reduce_pi(kv * (float)t);
        float cv = __cosf(rv), sv = __sinf(rv);
        int chunk = P >> 6, kk = P & 63;
        int r = m & 127;
        unsigned offc = swz((unsigned)(r * 128 + kk * 2));
        {   // cos row
            int tile = m >> 7;
            size_t base = (size_t)(tile * 2 + chunk) * 32768;
            __nv_bfloat16 hi = __float2bfloat16(cv);
            __nv_bfloat16 lo = __float2bfloat16(cv - __bfloat162float(hi));
            *(__nv_bfloat16*)(g_Apack + base + offc)         = hi;
            *(__nv_bfloat16*)(g_Apack + base + 16384 + offc) = lo;
        }
        {   // sin row (value -sin)
            float v = -sv;
            int tile = 64 + (m >> 7);
            size_t base = (size_t)(tile * 2 + chunk) * 32768;
            __nv_bfloat16 hi = __float2bfloat16(v);
            __nv_bfloat16 lo = __float2bfloat16(v - __bfloat162float(hi));
            *(__nv_bfloat16*)(g_Apack + base + offc)         = hi;
            *(__nv_bfloat16*)(g_Apack + base + 16384 + offc) = lo;
        }
    } else if (idx < Mm * 128 + Bb * 128 * NPIX) {
        int k = idx - Mm * 128;
        int b = k >> 15, rem = k & 32767;
        int t1 = rem >> 8, x = rem & 255;       // t1 = t-1
        int t = t1 + 1;
        const float* ib = img + (size_t)b * NPIX * NPIX;
        float top = (t < 128) ? ib[(128 + t) * NPIX + x] : 0.f;
        float bot = ib[(128 - t) * NPIX + x];
        float vS = top + bot, vA = top - bot;
        int chunk = t1 >> 6, kk = t1 & 63;
        unsigned off = swz((unsigned)(x * 128 + kk * 2));
        #pragma unroll
        for (int type = 0; type < 2; type++) {
            float v = type ? vA : vS;
            size_t base = (size_t)((b * 2 + type) * 2 + chunk) * 65536;
            __nv_bfloat16 hi = __float2bfloat16(v);
            __nv_bfloat16 lo = __float2bfloat16(v - __bfloat162float(hi));
            *(__nv_bfloat16*)(g_Bpack + base + off)         = hi;
            *(__nv_bfloat16*)(g_Bpack + base + 32768 + off) = lo;
        }
    } else {
        int k = idx - Mm * 128 - Bb * 128 * NPIX;
        if (k >= Bb * 128) return;
        int b = k >> 7, P = k & 127;
        const float* ir = img + ((size_t)b * NPIX + 128) * NPIX;
        float il = ir[lo_x(P)], ih = ir[hi_x(P)];
        g_IcF[k] = make_float2(il + ih, il - ih);
    }
}

// ---------------- main GEMM (mma.sync HMMA) + folded Eu epilogue ----------------
#define SMEM_STAGE 98304
#define SMEM_TOT   196608

__device__ __forceinline__ void load_chunk(uint32_t sb, int stage, int tile, int cc, int tid) {
    int b = cc >> 1, c = cc & 1;
    int type = (tile >= 64) ? 1 : 0;
    uint32_t dst = sb + stage * SMEM_STAGE;
    const float4* srcA = (const float4*)(g_Apack + (size_t)(tile * 2 + c) * 32768);
    #pragma unroll
    for (int i = 0; i < 4; i++) cpasync16(dst + (tid + i * 512) * 16, srcA + tid + i * 512);
    uint32_t dstB = dst + 32768;
    const float4* srcB = (const float4*)(g_Bpack + (size_t)((b * 2 + type) * 2 + c) * 65536);
    #pragma unroll
    for (int i = 0; i < 8; i++) cpasync16(dstB + (tid + i * 512) * 16, srcB + tid + i * 512);
    asm volatile("cp.async.commit_group;" ::: "memory");
}

__global__ __launch_bounds__(512, 1) void vis_mma_kernel() {
    extern __shared__ unsigned char smem[];
    uint32_t sb = smem_u32(smem);
    const int tid  = threadIdx.x;
    const int warp = tid >> 5, lane = tid & 31;
    const int wm   = warp & 3;
    const int wn   = warp >> 2;
    const int tile = blockIdx.x;
    const bool isCos = tile < 64;

    const uint32_t kA2 = (lane >> 4) * 16;
    const uint32_t kB2 = ((lane >> 3) & 1) * 16;
    uint32_t aRow[2], aXor[2], bRow[4], bXor[4];
    #pragma unroll
    for (int mt = 0; mt < 2; mt++) {
        int r = wm * 32 + mt * 16 + (lane & 15);
        aRow[mt] = r * 128;  aXor[mt] = (r & 7) << 4;
    }
    #pragma unroll
    for (int p = 0; p < 4; p++) {
        // column-within-warp q; alternate lo/hi mirror columns per pair
        int q  = p * 16 + ((lane >> 4) & 1) * 8 + (lane & 7);
        int nt = q >> 3, cc8 = q & 7;
        int P  = wn * 32 + nt * 4 + (cc8 >> 1);
        int x  = (cc8 & 1) ? hi_x(P) : lo_x(P);
        bRow[p] = x * 128;  bXor[p] = (x & 7) << 4;
    }

    float acc[64];
    #pragma unroll
    for (int i = 0; i < 64; i++) acc[i] = 0.f;

    load_chunk(sb, 0, tile, 0, tid);
    load_chunk(sb, 1, tile, 1, tid);

    for (int cc = 0; cc < 16; cc++) {
        const int s = cc & 1, b = cc >> 1, c = cc & 1;
        if (cc + 2 < 16) asm volatile("cp.async.wait_group 1;" ::: "memory");
        else             asm volatile("cp.async.wait_group 0;" ::: "memory");
        __syncthreads();

        const uint32_t st = sb + s * SMEM_STAGE;
        #pragma unroll
        for (int ks = 0; ks < 4; ks++) {
            uint32_t ah[2][4], al[2][4];
            #pragma unroll
            for (int mt = 0; mt < 2; mt++) {
                uint32_t k2 = ks * 32 + kA2;
                uint32_t offH = st +         aRow[mt] + (k2 ^ aXor[mt]);
                uint32_t offL = st + 16384 + aRow[mt] + (k2 ^ aXor[mt]);
                LDSM_X4(ah[mt][0], ah[mt][1], ah[mt][2], ah[mt][3], offH);
                LDSM_X4(al[mt][0], al[mt][1], al[mt][2], al[mt][3], offL);
            }
            #pragma unroll
            for (int p = 0; p < 4; p++) {
                uint32_t k2 = ks * 32 + kB2;
                uint32_t offBH = st + 32768 + bRow[p] + (k2 ^ bXor[p]);
                uint32_t offBL = st + 65536 + bRow[p] + (k2 ^ bXor[p]);
                uint32_t h0, h1, h2, h3, l0, l1, l2, l3;
                LDSM_X4(h0, h1, h2, h3, offBH);
                #pragma unroll
                for (int mt = 0; mt < 2; mt++) {
                    MMA_BF16(&acc[(mt * 8 + 2 * p) * 4],     ah[mt][0], ah[mt][1], ah[mt][2], ah[mt][3], h0, h1);
                    MMA_BF16(&acc[(mt * 8 + 2 * p + 1) * 4], ah[mt][0], ah[mt][1], ah[mt][2], ah[mt][3], h2, h3);
                    MMA_BF16(&acc[(mt * 8 + 2 * p) * 4],     al[mt][0], al[mt][1], al[mt][2], al[mt][3], h0, h1);
                    MMA_BF16(&acc[(mt * 8 + 2 * p + 1) * 4], al[mt][0], al[mt][1], al[mt][2], al[mt][3], h2, h3);
                }
                LDSM_X4(l0, l1, l2, l3, offBL);
                #pragma unroll
                for (int mt = 0; mt < 2; mt++) {
                    MMA_BF16(&acc[(mt * 8 + 2 * p) * 4],     ah[mt][0], ah[mt][1], ah[mt][2], ah[mt][3], l0, l1);
                    MMA_BF16(&acc[(mt * 8 + 2 * p + 1) * 4], ah[mt][0], ah[mt][1], ah[mt][2], ah[mt][3], l2, l3);
                }
            }
        }
        __syncthreads();                     // all warps done reading stage s
        if (cc + 2 < 16) load_chunk(sb, s, tile, cc + 2, tid);   // overlap refill with epilogue

        if (c == 1) {
            const int g = lane >> 2, t4 = lane & 3;
            const bool special = (wn == 3) && (t4 == 3);
            #pragma unroll
            for (int mt = 0; mt < 2; mt++) {
                int r0 = tile * 128 + wm * 32 + mt * 16 + g;
                int mA = r0 & (Mm - 1);
                int mB = (r0 + 8) & (Mm - 1);
                const float2* tcA = g_EuF + (size_t)mA * 128;
                const float2* tcB = g_EuF + (size_t)mB * 128;
                float p1a = 0.f, p2a = 0.f, p1b = 0.f, p2b = 0.f;
                #pragma unroll
                for (int nt = 0; nt < 8; nt++) {
                    int P = wn * 32 + nt * 4 + t4;
                    float2 csA = tcA[P];
                    float2 csB = tcB[P];
                    float* d = &acc[(mt * 8 + nt) * 4];
                    float s0 = d[0] + d[1], a0 = d[0] - d[1];
                    float s1 = d[2] + d[3], a1 = d[2] - d[3];
                    float tHa = d[1], tHb = d[3];
                    if (isCos) {
                        float2 ic = g_IcF[b * 128 + P];
                        s0 += ic.x;  a0 += ic.y;  s1 += ic.x;  a1 += ic.y;
                        float ih = 0.5f * (ic.x - ic.y);
                        tHa += ih;  tHb += ih;
                    }
                    p1a = fmaf(s0, csA.x, p1a);  p2a = fmaf(a0, csA.y, p2a);
                    p1b = fmaf(s1, csB.x, p1b);  p2b = fmaf(a1, csB.y, p2b);
                    if (special && nt == 7) {
                        // pair (x=0, x=128): generic used (C,S)=(cos128ku,sin128ku);
                        // true x=128 coeffs are (1,0) -> fixup with tH = t[128]
                        p1a = fmaf(tHa, 1.f - csA.x, p1a);  p2a = fmaf(tHa, csA.y, p2a);
                        p1b = fmaf(tHb, 1.f - csB.x, p1b);  p2b = fmaf(tHb, csB.y, p2b);
                    }
                    d[0] = d[1] = d[2] = d[3] = 0.f;
                }
                #pragma unroll
                for (int sh = 1; sh <= 2; sh <<= 1) {
                    p1a += __shfl_xor_sync(0xffffffffu, p1a, sh);
                    p2a += __shfl_xor_sync(0xffffffffu, p2a, sh);
                    p1b += __shfl_xor_sync(0xffffffffu, p1b, sh);
                    p2b += __shfl_xor_sync(0xffffffffu, p2b, sh);
                }
                if (t4 == 0) {
                    size_t i1 = ((size_t)r0 * Bb + b) * 4 + wn;
                    size_t i2 = ((size_t)(r0 + 8) * Bb + b) * 4 + wn;
                    g_p1[i1] = p1a;  g_p2[i1] = p2a;
                    g_p1[i2] = p1b;  g_p2[i2] = p2b;
                }
            }
        }
    }
}

// ---------------- combine: partials -> kdata -> vis, visamp, visc ----------------
__global__ void combine_kernel(const float* __restrict__ pf, float* __restrict__ out) {
    int idx = blockIdx.x * blockDim.x + threadIdx.x;
    if (idx >= Bb * Mm) return;
    int b = idx >> 13, m = idx & (Mm - 1);
    size_t i1 = ((size_t)m * Bb + b) * 4;
    size_t i2 = ((size_t)(m + Mm) * Bb + b) * 4;
    float4 q1 = *(const float4*)(g_p1 + i1);
    float4 q2 = *(const float4*)(g_p2 + i1);
    float4 q3 = *(const float4*)(g_p1 + i2);
    float4 q4 = *(const float4*)(g_p2 + i2);
    float trr = q1.x + q1.y + q1.z + q1.w;
    float tri = q2.x + q2.y + q2.z + q2.w;
    float tir = q3.x + q3.y + q3.z + q3.w;
    float tii = q4.x + q4.y + q4.z + q4.w;
    float kr = trr - tii, ki = tri + tir;
    float pr = pf[m], pi = pf[Mm + m];
    float vr = kr * pr - ki * pi;
    float vi = kr * pi + ki * pr;
    out[(size_t)b * 2 * Mm + m]      = vr;
    out[(size_t)b * 2 * Mm + Mm + m] = vi;
    out[(size_t)Bb * 2 * Mm + (size_t)b * Mm + m] = sqrtf(vr * vr + vi * vi + 1e-16f);
    g_visc[(size_t)b * Mm + m] = make_float2(vr, vi);
}

// ---------------- fused cphase + logcamp ----------------
__global__ void obs_kernel(const float* __restrict__ sign, const int* __restrict__ cind,
                           const int* __restrict__ aind,
                           float* __restrict__ out_cp, float* __restrict__ out_lc) {
    int idx = blockIdx.x * blockDim.x + threadIdx.x;
    if (idx < Bb * N_CP) {
        int b = idx / N_CP, n = idx - b * N_CP;
        const float2* vb = g_visc + (size_t)b * Mm;
        float s = 0.f;
        #pragma unroll
        for (int k = 0; k < 3; k++) {
            float2 v = vb[cind[k * N_CP + n]];
            s = fmaf(sign[k * N_CP + n], fast_atan2(v.y, v.x), s);
        }
        out_cp[idx] = s * 57.29577951308232f;
    } else {
        int j = idx - Bb * N_CP;
        if (j >= Bb * N_CA) return;
        int b = j / N_CA, n = j - b * N_CA;
        const float2* vb = g_visc + (size_t)b * Mm;
        float s[4];
        #pragma unroll
        for (int k = 0; k < 4; k++) {
            float2 v = vb[aind[k * N_CA + n]];
            s[k] = fmaf(v.x, v.x, fmaf(v.y, v.y, 1e-16f));
        }
        out_lc[j] = 0.5f * (__logf(s[0]) + __logf(s[1]) - __logf(s[2]) - __logf(s[3]));
    }
}

extern "C" void kernel_launch(void* const* d_in, const int* in_sizes, int n_in,
                              void* d_out, int out_size) {
    const float* images      = (const float*)d_in[0];
    const float* ktraj       = (const float*)d_in[1];
    const float* pulsefac    = (const float*)d_in[2];
    const float* cphase_sign = (const float*)d_in[3];
    const int*   cphase_ind  = (const int*)d_in[4];
    const int*   camp_ind    = (const int*)d_in[5];
    float* out = (float*)d_out;

    float* out_cp = out + (size_t)Bb * 2 * Mm + (size_t)Bb * Mm;
    float* out_lc = out_cp + (size_t)Bb * N_CP;

    cudaFuncSetAttribute(vis_mma_kernel, cudaFuncAttributeMaxDynamicSharedMemorySize, SMEM_TOT);

    int prep_n = Mm * 128 + Bb * 128 * NPIX + Bb * 128;
    prep_kernel<<<(prep_n + 255) / 256, 256>>>(ktraj, images);
    vis_mma_kernel<<<TILES, 512, SMEM_TOT>>>();
    combine_kernel<<<(Bb * Mm + 255) / 256, 256>>>(pulsefac, out);
    obs_kernel<<<(Bb * (N_CP + N_CA) + 255) / 256, 256>>>(cphase_sign, cphase_ind, camp_ind,
                                                          out_cp, out_lc);
}